// round 15
// baseline (speedup 1.0000x reference)
#include <cuda_runtime.h>
#include <cuda_bf16.h>
#include <cstdint>

#define B_ 512
#define T_ 8
#define D_ 512
#define H_ 512
#define LAT_ 64
#define H2_ 1024
#define H3_ 1536
#define NCTA 128
#define NTHR 512

// smem: 3 stages x 4 buffers(Ahi,Alo,Whi,Wlo) x 64 rows x 40 bf16 (80B stride)
#define BUFSZ 5120
#define SSZ (4 * BUFSZ)
#define SMEM_TOTAL (3 * SSZ)

// ---------------- persistent device scratch ----------------
__device__ __align__(16) float g_h[B_ * H_];
__device__ __align__(16) float g_kacc[B_ * H_];
__device__ __align__(16) float g_gh[B_ * H3_];
__device__ __align__(16) float g_gi[B_ * T_ * H3_];
__device__ __align__(16) float g_t0[B_ * T_];
__device__ __align__(16) float g_dt[B_ * T_];
__device__ __align__(16) float g_w1t[H2_];
__device__ unsigned long long g_bar;

__device__ __align__(16) __nv_bfloat16 g_h_hi[B_ * H_], g_h_lo[B_ * H_];
__device__ __align__(16) __nv_bfloat16 g_hin_hi[B_ * H_], g_hin_lo[B_ * H_];
__device__ __align__(16) __nv_bfloat16 g_a1hi[B_ * H2_], g_a1lo[B_ * H2_];
__device__ __align__(16) __nv_bfloat16 g_a2hi[B_ * H2_], g_a2lo[B_ * H2_];
__device__ __align__(16) __nv_bfloat16 g_x_hi[B_ * T_ * D_], g_x_lo[B_ * T_ * D_];

__device__ __align__(16) __nv_bfloat16 g_W1hi[H2_ * H_], g_W1lo[H2_ * H_];
__device__ __align__(16) __nv_bfloat16 g_W2hi[H2_ * H2_], g_W2lo[H2_ * H2_];
__device__ __align__(16) __nv_bfloat16 g_W3hi[H_ * H2_], g_W3lo[H_ * H2_];
__device__ __align__(16) __nv_bfloat16 g_Wihhi[H3_ * D_], g_Wihlo[H3_ * D_];
__device__ __align__(16) __nv_bfloat16 g_Whhhi[H3_ * H_], g_Whhlo[H3_ * H_];
__device__ __align__(16) __nv_bfloat16 g_Wouthi[2 * LAT_ * H_], g_Woutlo[2 * LAT_ * H_];

// ---------------- prep kernels ----------------
__global__ void k_split(const float* __restrict__ src, __nv_bfloat16* __restrict__ hi,
                        __nv_bfloat16* __restrict__ lo, int n) {
    int i = blockIdx.x * blockDim.x + threadIdx.x;
    if (i >= n) return;
    float v = src[i];
    __nv_bfloat16 h = __float2bfloat16(v);
    hi[i] = h;
    lo[i] = __float2bfloat16(v - __bfloat162float(h));
}

__global__ void k_split_w1(const float* __restrict__ W1) {
    int i = blockIdx.x * blockDim.x + threadIdx.x;
    if (i < H2_ * H_) {
        int r = i >> 9, c = i & (H_ - 1);
        float v = W1[r * (H_ + 1) + c];
        __nv_bfloat16 h = __float2bfloat16(v);
        g_W1hi[i] = h;
        g_W1lo[i] = __float2bfloat16(v - __bfloat162float(h));
    }
    if (i < H2_) g_w1t[i] = W1[i * (H_ + 1) + H_];
}

__global__ void k_tprep(const float* __restrict__ ts) {
    int i = blockIdx.x * blockDim.x + threadIdx.x;
    if (i >= B_ * T_) return;
    int b = i / T_, t = i % T_;
    float t1 = ts[b * T_ + t];
    float t0 = (t == 0) ? ts[b * T_] : ts[b * T_ + t - 1];
    g_t0[i] = t0;
    g_dt[i] = (t1 - t0) * 0.25f;
}

__global__ void k_reset() {
    int i = blockIdx.x * blockDim.x + threadIdx.x;
    if (i == 0) g_bar = 0ull;
    if (i < B_ * H_) {
        g_h[i] = 0.0f;
        __nv_bfloat16 z = __float2bfloat16(0.0f);
        g_h_hi[i] = z;
        g_h_lo[i] = z;
    }
}

// ---------------- device helpers ----------------
__device__ __forceinline__ void cp16cg(void* s, const void* g) {
    unsigned sa = (unsigned)__cvta_generic_to_shared(s);
    asm volatile("cp.async.cg.shared.global [%0], [%1], 16;\n" ::"r"(sa), "l"(g));
}
__device__ __forceinline__ void cp16ca(void* s, const void* g) {
    unsigned sa = (unsigned)__cvta_generic_to_shared(s);
    asm volatile("cp.async.ca.shared.global [%0], [%1], 16;\n" ::"r"(sa), "l"(g));
}
__device__ __forceinline__ void ldsm4(unsigned* r, uint32_t a) {
    asm volatile("ldmatrix.sync.aligned.m8n8.x4.shared.b16 {%0,%1,%2,%3}, [%4];"
                 : "=r"(r[0]), "=r"(r[1]), "=r"(r[2]), "=r"(r[3])
                 : "r"(a));
}
__device__ __forceinline__ void ldsm2(unsigned* r, uint32_t a) {
    asm volatile("ldmatrix.sync.aligned.m8n8.x2.shared.b16 {%0,%1}, [%2];"
                 : "=r"(r[0]), "=r"(r[1])
                 : "r"(a));
}
__device__ __forceinline__ void mma16816(float* c, const unsigned* a, unsigned b0,
                                         unsigned b1) {
    asm volatile(
        "mma.sync.aligned.m16n8k16.row.col.f32.bf16.bf16.f32 "
        "{%0,%1,%2,%3}, {%4,%5,%6,%7}, {%8,%9}, {%0,%1,%2,%3};\n"
        : "+f"(c[0]), "+f"(c[1]), "+f"(c[2]), "+f"(c[3])
        : "r"(a[0]), "r"(a[1]), "r"(a[2]), "r"(a[3]), "r"(b0), "r"(b1));
}
__device__ __forceinline__ void split_store2(__nv_bfloat16* Hi, __nv_bfloat16* Lo, int o,
                                             float v0, float v1) {
    __nv_bfloat16 h0 = __float2bfloat16(v0), h1 = __float2bfloat16(v1);
    *(__nv_bfloat162*)&Hi[o] = __halves2bfloat162(h0, h1);
    __nv_bfloat16 l0 = __float2bfloat16(v0 - __bfloat162float(h0));
    __nv_bfloat16 l1 = __float2bfloat16(v1 - __bfloat162float(h1));
    *(__nv_bfloat162*)&Lo[o] = __halves2bfloat162(l0, l1);
}

__device__ __forceinline__ void gbar(unsigned long long& target) {
    __syncthreads();
    if (threadIdx.x == 0) {
        target += NCTA;
        __threadfence();
        atomicAdd(&g_bar, 1ull);
        unsigned long long v;
        do {
            asm volatile("ld.acquire.gpu.global.u64 %0, [%1];" : "=l"(v) : "l"(&g_bar));
            if (v < target) __nanosleep(32);
        } while (v < target);
    }
    __syncthreads();
}

// ---------------- GEMM phase: C[M,N] = epi(A @ W^T), bf16 hi/lo pairs ----------------
// 16 warps: warp row = warp>>2 (4 x 16 rows), warp col = warp&3 (4 x TN/4 cols)
// mode 0: +bias -> fp32 C ; 1: swish(+bias) ; 2: swish(+bias + t*w1t) ; 3..6: RK4 stages
template <int TN>
__device__ __noinline__ void gemm_phase(
    const __nv_bfloat16* __restrict__ Ahi, const __nv_bfloat16* __restrict__ Alo,
    const __nv_bfloat16* __restrict__ Whi, const __nv_bfloat16* __restrict__ Wlo,
    const float* __restrict__ bias, float* Cf, __nv_bfloat16* Ohi, __nv_bfloat16* Olo,
    int M, int N, int K, int mode, int tstep, float spc, char* dsm, uint32_t smb) {
    const int tid = threadIdx.x, lane = tid & 31, warp = tid >> 5;
    constexpr int NI = TN / 32;  // n8 tiles per warp (64 -> 2, 32 -> 1)
    const int ncols = N / TN;
    const int ntiles = (M / 64) * ncols;
    const int nk = K / 32;

    const int wm = (warp >> 2) * 16;
    const int wn = (warp & 3) * (TN / 4);

    // ldmatrix per-lane offsets (stride-40 bf16 rows = 80 bytes, conflict-free)
    const uint32_t aoff = (uint32_t)(wm + (lane & 15)) * 80 + (uint32_t)(lane >> 4) * 16;
    uint32_t boff;
    if (TN == 64)
        boff = (uint32_t)(wn + (lane & 15)) * 80 + (uint32_t)(lane >> 4) * 16;
    else
        boff = (uint32_t)(wn + (lane & 7)) * 80 + (uint32_t)((lane >> 3) & 1) * 16;

    for (int tile = blockIdx.x; tile < ntiles; tile += NCTA) {
        const int rowBase = (tile / ncols) * 64;
        const int colBase = (tile % ncols) * TN;

        float acc[NI][4];
#pragma unroll
        for (int ni = 0; ni < NI; ni++)
#pragma unroll
            for (int e = 0; e < 4; e++) acc[ni][e] = 0.0f;

        // fill: threads 0-255 do A (hi+lo), threads 256-511 do W (hi+lo); 1 cp each buf
        auto fill = [&](int st, int k0) {
            char* sst = dsm + st * SSZ;
            const int grp = tid >> 8;
            const int i = tid & 255;
            const int r = i >> 2, ch = i & 3;
            const unsigned o = (unsigned)r * 80 + (unsigned)ch * 16;
            if (grp == 0) {
                const size_t gA = (size_t)(rowBase + r) * K + k0 + ch * 8;
                cp16cg(sst + o, Ahi + gA);
                cp16cg(sst + BUFSZ + o, Alo + gA);
            } else if (TN == 64 || r < 32) {
                const size_t gW = (size_t)(colBase + r) * K + k0 + ch * 8;
                cp16ca(sst + 2 * BUFSZ + o, Whi + gW);
                cp16ca(sst + 3 * BUFSZ + o, Wlo + gW);
            }
            asm volatile("cp.async.commit_group;\n" ::);
        };

        __syncthreads();  // protect stages from previous tile's lagging reads
        fill(0, 0);
        fill(1, 32);

        for (int kt = 0; kt < nk; ++kt) {
            if (kt < nk - 1)
                asm volatile("cp.async.wait_group 1;\n" ::);
            else
                asm volatile("cp.async.wait_group 0;\n" ::);
            __syncthreads();
            if (kt + 2 < nk) fill((kt + 2) % 3, (kt + 2) * 32);
            const uint32_t sb = smb + (uint32_t)(kt % 3) * SSZ;
#pragma unroll
            for (int kk = 0; kk < 2; kk++) {
                const uint32_t cb = sb + kk * 32;
                unsigned ah[4], al[4], bh[4], bl[4];
                ldsm4(ah, cb + aoff);
                ldsm4(al, cb + BUFSZ + aoff);
                if (TN == 64) {
                    ldsm4(bh, cb + 2 * BUFSZ + boff);
                    ldsm4(bl, cb + 3 * BUFSZ + boff);
                } else {
                    ldsm2(bh, cb + 2 * BUFSZ + boff);
                    ldsm2(bl, cb + 3 * BUFSZ + boff);
                }
#pragma unroll
                for (int ni = 0; ni < NI; ni++) {
                    const unsigned bh0 = (TN == 64) ? bh[ni] : bh[0];
                    const unsigned bh1 = (TN == 64) ? bh[ni + 2] : bh[1];
                    const unsigned bl0 = (TN == 64) ? bl[ni] : bl[0];
                    const unsigned bl1 = (TN == 64) ? bl[ni + 2] : bl[1];
                    mma16816(acc[ni], ah, bh0, bh1);
                    mma16816(acc[ni], ah, bl0, bl1);
                    mma16816(acc[ni], al, bh0, bh1);
                }
            }
        }

        // epilogue: warp owns rows [rowBase+wm, +16), cols [colBase+wn, +TN/4)
#pragma unroll
        for (int half = 0; half < 2; half++) {
            int rr = rowBase + wm + (lane >> 2) + half * 8;
            float tval = 0.0f, dtv = 0.0f;
            if (mode == 2) tval = g_t0[rr * T_ + tstep] + spc * g_dt[rr * T_ + tstep];
            if (mode >= 3) dtv = g_dt[rr * T_ + tstep];
#pragma unroll
            for (int ni = 0; ni < NI; ni++) {
                int c = colBase + wn + ni * 8 + (lane & 3) * 2;
                float v0 = acc[ni][half * 2 + 0] + bias[c];
                float v1 = acc[ni][half * 2 + 1] + bias[c + 1];
                if (mode == 0) {
                    float2 o2 = make_float2(v0, v1);
                    *(float2*)&Cf[(size_t)rr * N + c] = o2;
                } else if (mode <= 2) {
                    if (mode == 2) {
                        v0 += tval * g_w1t[c];
                        v1 += tval * g_w1t[c + 1];
                    }
                    v0 = v0 / (1.0f + __expf(-v0));
                    v1 = v1 / (1.0f + __expf(-v1));
                    split_store2(Ohi, Olo, rr * N + c, v0, v1);
                } else {
                    int o = rr * H_ + c;
                    float h0 = __ldcg(&g_h[o]), h1 = __ldcg(&g_h[o + 1]);
                    if (mode == 3) {
                        g_kacc[o] = v0;
                        g_kacc[o + 1] = v1;
                        split_store2(g_hin_hi, g_hin_lo, o, h0 + 0.5f * dtv * v0,
                                     h1 + 0.5f * dtv * v1);
                    } else if (mode == 4) {
                        g_kacc[o] = __ldcg(&g_kacc[o]) + 2.0f * v0;
                        g_kacc[o + 1] = __ldcg(&g_kacc[o + 1]) + 2.0f * v1;
                        split_store2(g_hin_hi, g_hin_lo, o, h0 + 0.5f * dtv * v0,
                                     h1 + 0.5f * dtv * v1);
                    } else if (mode == 5) {
                        g_kacc[o] = __ldcg(&g_kacc[o]) + 2.0f * v0;
                        g_kacc[o + 1] = __ldcg(&g_kacc[o + 1]) + 2.0f * v1;
                        split_store2(g_hin_hi, g_hin_lo, o, h0 + dtv * v0, h1 + dtv * v1);
                    } else {
                        float n0 = h0 + (dtv * (1.0f / 6.0f)) * (__ldcg(&g_kacc[o]) + v0);
                        float n1 = h1 + (dtv * (1.0f / 6.0f)) * (__ldcg(&g_kacc[o + 1]) + v1);
                        g_h[o] = n0;
                        g_h[o + 1] = n1;
                        split_store2(g_h_hi, g_h_lo, o, n0, n1);
                    }
                }
            }
        }
    }
}

__device__ void gate_phase(int t) {
    for (int i = blockIdx.x * NTHR + threadIdx.x; i < B_ * H_; i += NCTA * NTHR) {
        int b = i >> 9, j = i & (H_ - 1);
        const float* gi = g_gi + (size_t)(b * T_ + t) * H3_;
        const float* gh = g_gh + (size_t)b * H3_;
        float ir = __ldcg(&gi[j]), iz = __ldcg(&gi[j + H_]), in = __ldcg(&gi[j + 2 * H_]);
        float hr = __ldcg(&gh[j]), hz = __ldcg(&gh[j + H_]), hn = __ldcg(&gh[j + 2 * H_]);
        float r = 1.0f / (1.0f + expf(-(ir + hr)));
        float z = 1.0f / (1.0f + expf(-(iz + hz)));
        float n = tanhf(in + r * hn);
        float h = (1.0f - z) * n + z * __ldcg(&g_h[i]);
        g_h[i] = h;
        __nv_bfloat16 hh = __float2bfloat16(h);
        g_h_hi[i] = hh;
        g_h_lo[i] = __float2bfloat16(h - __bfloat162float(hh));
    }
}

__global__ void __launch_bounds__(NTHR, 1) k_persist(
    const float* __restrict__ bih, const float* __restrict__ bhh, const float* __restrict__ b1,
    const float* __restrict__ b2, const float* __restrict__ b3, const float* __restrict__ bout,
    float* __restrict__ out) {
    extern __shared__ char dsm[];
    const uint32_t smb = (uint32_t)__cvta_generic_to_shared(dsm);
    unsigned long long bt = 0;

    // gi = x @ Wih^T + bih for all (b,t)
    gemm_phase<64>(g_x_hi, g_x_lo, g_Wihhi, g_Wihlo, bih, g_gi, nullptr, nullptr, B_ * T_, H3_,
                   D_, 0, 0, 0.0f, dsm, smb);
    gbar(bt);

#pragma unroll 1
    for (int t = 0; t < T_; t++) {
#pragma unroll 1
        for (int s = 0; s < 4; s++) {
#pragma unroll 1
            for (int e = 0; e < 4; e++) {
                float spc = (float)s + ((e == 1 || e == 2) ? 0.5f : (e == 3 ? 1.0f : 0.0f));
                const __nv_bfloat16* Ah = e ? g_hin_hi : g_h_hi;
                const __nv_bfloat16* Al = e ? g_hin_lo : g_h_lo;
                gemm_phase<64>(Ah, Al, g_W1hi, g_W1lo, b1, nullptr, g_a1hi, g_a1lo, B_, H2_, H_,
                               2, t, spc, dsm, smb);
                gbar(bt);
                gemm_phase<64>(g_a1hi, g_a1lo, g_W2hi, g_W2lo, b2, nullptr, g_a2hi, g_a2lo, B_,
                               H2_, H2_, 1, t, 0.0f, dsm, smb);
                gbar(bt);
                gemm_phase<32>(g_a2hi, g_a2lo, g_W3hi, g_W3lo, b3, nullptr, nullptr, nullptr,
                               B_, H_, H2_, 3 + e, t, 0.0f, dsm, smb);
                gbar(bt);
            }
        }
        gemm_phase<32>(g_h_hi, g_h_lo, g_Whhhi, g_Whhlo, bhh, g_gh, nullptr, nullptr, B_, H3_,
                       H_, 0, 0, 0.0f, dsm, smb);
        gbar(bt);
        gate_phase(t);
        gbar(bt);
    }

    // out = h @ Wout^T + bout
    gemm_phase<32>(g_h_hi, g_h_lo, g_Wouthi, g_Woutlo, bout, out, nullptr, nullptr, B_,
                   2 * LAT_, H_, 0, 0, 0.0f, dsm, smb);
    // h and c tail regions
    for (int i = blockIdx.x * NTHR + threadIdx.x; i < B_ * H_; i += NCTA * NTHR) {
        out[B_ * 2 * LAT_ + i] = __ldcg(&g_h[i]);
        out[B_ * 2 * LAT_ + B_ * H_ + i] = 0.0f;
    }
}

// ---------------- host ----------------
template <typename Tp>
static Tp* symaddr(const void* sym) {
    void* p = nullptr;
    cudaGetSymbolAddress(&p, sym);
    return (Tp*)p;
}

extern "C" void kernel_launch(void* const* d_in, const int* in_sizes, int n_in,
                              void* d_out, int out_size) {
    const float* x    = (const float*)d_in[0];
    const float* ts   = (const float*)d_in[1];
    const float* Wih  = (const float*)d_in[2];
    const float* Whh  = (const float*)d_in[3];
    const float* bih  = (const float*)d_in[4];
    const float* bhh  = (const float*)d_in[5];
    const float* Wout = (const float*)d_in[6];
    const float* bout = (const float*)d_in[7];
    const float* W1   = (const float*)d_in[8];
    const float* b1   = (const float*)d_in[9];
    const float* W2   = (const float*)d_in[10];
    const float* b2   = (const float*)d_in[11];
    const float* W3   = (const float*)d_in[12];
    const float* b3   = (const float*)d_in[13];
    float* out = (float*)d_out;

    cudaFuncSetAttribute(k_persist, cudaFuncAttributeMaxDynamicSharedMemorySize, SMEM_TOTAL);

    const int TPB = 256;
    k_split<<<(H3_ * D_ + TPB - 1) / TPB, TPB>>>(Wih, symaddr<__nv_bfloat16>(g_Wihhi),
                                                 symaddr<__nv_bfloat16>(g_Wihlo), H3_ * D_);
    k_split<<<(H3_ * H_ + TPB - 1) / TPB, TPB>>>(Whh, symaddr<__nv_bfloat16>(g_Whhhi),
                                                 symaddr<__nv_bfloat16>(g_Whhlo), H3_ * H_);
    k_split<<<(H2_ * H2_ + TPB - 1) / TPB, TPB>>>(W2, symaddr<__nv_bfloat16>(g_W2hi),
                                                  symaddr<__nv_bfloat16>(g_W2lo), H2_ * H2_);
    k_split<<<(H_ * H2_ + TPB - 1) / TPB, TPB>>>(W3, symaddr<__nv_bfloat16>(g_W3hi),
                                                 symaddr<__nv_bfloat16>(g_W3lo), H_ * H2_);
    k_split<<<(2 * LAT_ * H_ + TPB - 1) / TPB, TPB>>>(Wout, symaddr<__nv_bfloat16>(g_Wouthi),
                                                      symaddr<__nv_bfloat16>(g_Woutlo),
                                                      2 * LAT_ * H_);
    k_split<<<(B_ * T_ * D_ + TPB - 1) / TPB, TPB>>>(x, symaddr<__nv_bfloat16>(g_x_hi),
                                                     symaddr<__nv_bfloat16>(g_x_lo),
                                                     B_ * T_ * D_);
    k_split_w1<<<(H2_ * H_ + TPB - 1) / TPB, TPB>>>(W1);
    k_tprep<<<(B_ * T_ + TPB - 1) / TPB, TPB>>>(ts);
    k_reset<<<(B_ * H_ + TPB - 1) / TPB, TPB>>>();

    k_persist<<<NCTA, NTHR, SMEM_TOTAL>>>(bih, bhh, b1, b2, b3, bout, out);
}

// round 16
// speedup vs baseline: 1.2397x; 1.2397x over previous
#include <cuda_runtime.h>
#include <cuda_bf16.h>
#include <cstdint>

#define B_ 512
#define T_ 8
#define D_ 512
#define H_ 512
#define LAT_ 64
#define H2_ 1024
#define H3_ 1536
#define NCTA 128
#define NTHR 256

// smem: 3 stages x 4 buffers(Ahi,Alo,Whi,Wlo) x 64 rows x 72 bf16 (144B stride, Kc=64)
#define ROWB 144
#define BUFSZ (64 * ROWB)
#define SSZ (4 * BUFSZ)
#define SMEM_TOTAL (3 * SSZ)

// ---------------- persistent device scratch ----------------
__device__ __align__(16) float g_h[B_ * H_];
__device__ __align__(16) float g_kacc[B_ * H_];
__device__ __align__(16) float g_gh[B_ * H3_];
__device__ __align__(16) float g_gi[B_ * T_ * H3_];
__device__ __align__(16) float g_t0[B_ * T_];
__device__ __align__(16) float g_dt[B_ * T_];
__device__ __align__(16) float g_w1t[H2_];
__device__ unsigned long long g_bar;

__device__ __align__(16) __nv_bfloat16 g_h_hi[B_ * H_], g_h_lo[B_ * H_];
__device__ __align__(16) __nv_bfloat16 g_hin_hi[B_ * H_], g_hin_lo[B_ * H_];
__device__ __align__(16) __nv_bfloat16 g_a1hi[B_ * H2_], g_a1lo[B_ * H2_];
__device__ __align__(16) __nv_bfloat16 g_a2hi[B_ * H2_], g_a2lo[B_ * H2_];
__device__ __align__(16) __nv_bfloat16 g_x_hi[B_ * T_ * D_], g_x_lo[B_ * T_ * D_];

__device__ __align__(16) __nv_bfloat16 g_W1hi[H2_ * H_], g_W1lo[H2_ * H_];
__device__ __align__(16) __nv_bfloat16 g_W2hi[H2_ * H2_], g_W2lo[H2_ * H2_];
__device__ __align__(16) __nv_bfloat16 g_W3hi[H_ * H2_], g_W3lo[H_ * H2_];
__device__ __align__(16) __nv_bfloat16 g_Wihhi[H3_ * D_], g_Wihlo[H3_ * D_];
__device__ __align__(16) __nv_bfloat16 g_Whhhi[H3_ * H_], g_Whhlo[H3_ * H_];
__device__ __align__(16) __nv_bfloat16 g_Wouthi[2 * LAT_ * H_], g_Woutlo[2 * LAT_ * H_];

// ---------------- prep kernels ----------------
__global__ void k_split(const float* __restrict__ src, __nv_bfloat16* __restrict__ hi,
                        __nv_bfloat16* __restrict__ lo, int n) {
    int i = blockIdx.x * blockDim.x + threadIdx.x;
    if (i >= n) return;
    float v = src[i];
    __nv_bfloat16 h = __float2bfloat16(v);
    hi[i] = h;
    lo[i] = __float2bfloat16(v - __bfloat162float(h));
}

__global__ void k_split_w1(const float* __restrict__ W1) {
    int i = blockIdx.x * blockDim.x + threadIdx.x;
    if (i < H2_ * H_) {
        int r = i >> 9, c = i & (H_ - 1);
        float v = W1[r * (H_ + 1) + c];
        __nv_bfloat16 h = __float2bfloat16(v);
        g_W1hi[i] = h;
        g_W1lo[i] = __float2bfloat16(v - __bfloat162float(h));
    }
    if (i < H2_) g_w1t[i] = W1[i * (H_ + 1) + H_];
}

__global__ void k_tprep(const float* __restrict__ ts) {
    int i = blockIdx.x * blockDim.x + threadIdx.x;
    if (i >= B_ * T_) return;
    int b = i / T_, t = i % T_;
    float t1 = ts[b * T_ + t];
    float t0 = (t == 0) ? ts[b * T_] : ts[b * T_ + t - 1];
    g_t0[i] = t0;
    g_dt[i] = (t1 - t0) * 0.25f;
}

__global__ void k_reset() {
    int i = blockIdx.x * blockDim.x + threadIdx.x;
    if (i == 0) g_bar = 0ull;
    if (i < B_ * H_) {
        g_h[i] = 0.0f;
        __nv_bfloat16 z = __float2bfloat16(0.0f);
        g_h_hi[i] = z;
        g_h_lo[i] = z;
    }
}

// ---------------- device helpers ----------------
__device__ __forceinline__ void cp16cg(void* s, const void* g) {
    unsigned sa = (unsigned)__cvta_generic_to_shared(s);
    asm volatile("cp.async.cg.shared.global [%0], [%1], 16;\n" ::"r"(sa), "l"(g));
}
__device__ __forceinline__ void cp16ca(void* s, const void* g) {
    unsigned sa = (unsigned)__cvta_generic_to_shared(s);
    asm volatile("cp.async.ca.shared.global [%0], [%1], 16;\n" ::"r"(sa), "l"(g));
}
__device__ __forceinline__ void ldsm4(unsigned* r, uint32_t a) {
    asm volatile("ldmatrix.sync.aligned.m8n8.x4.shared.b16 {%0,%1,%2,%3}, [%4];"
                 : "=r"(r[0]), "=r"(r[1]), "=r"(r[2]), "=r"(r[3])
                 : "r"(a));
}
__device__ __forceinline__ void ldsm2(unsigned* r, uint32_t a) {
    asm volatile("ldmatrix.sync.aligned.m8n8.x2.shared.b16 {%0,%1}, [%2];"
                 : "=r"(r[0]), "=r"(r[1])
                 : "r"(a));
}
__device__ __forceinline__ void mma16816(float* c, const unsigned* a, unsigned b0,
                                         unsigned b1) {
    asm volatile(
        "mma.sync.aligned.m16n8k16.row.col.f32.bf16.bf16.f32 "
        "{%0,%1,%2,%3}, {%4,%5,%6,%7}, {%8,%9}, {%0,%1,%2,%3};\n"
        : "+f"(c[0]), "+f"(c[1]), "+f"(c[2]), "+f"(c[3])
        : "r"(a[0]), "r"(a[1]), "r"(a[2]), "r"(a[3]), "r"(b0), "r"(b1));
}
__device__ __forceinline__ void split_store2(__nv_bfloat16* Hi, __nv_bfloat16* Lo, int o,
                                             float v0, float v1) {
    __nv_bfloat16 h0 = __float2bfloat16(v0), h1 = __float2bfloat16(v1);
    *(__nv_bfloat162*)&Hi[o] = __halves2bfloat162(h0, h1);
    __nv_bfloat16 l0 = __float2bfloat16(v0 - __bfloat162float(h0));
    __nv_bfloat16 l1 = __float2bfloat16(v1 - __bfloat162float(h1));
    *(__nv_bfloat162*)&Lo[o] = __halves2bfloat162(l0, l1);
}

__device__ __forceinline__ void gbar(unsigned long long& target) {
    __syncthreads();
    if (threadIdx.x == 0) {
        target += NCTA;
        __threadfence();
        atomicAdd(&g_bar, 1ull);
        unsigned long long v;
        do {
            asm volatile("ld.acquire.gpu.global.u64 %0, [%1];" : "=l"(v) : "l"(&g_bar));
            if (v < target) __nanosleep(32);
        } while (v < target);
    }
    __syncthreads();
}

// ---------------- GEMM phase: C[M,N] = epi(A @ W^T), bf16 hi/lo pairs ----------------
// 8 warps: warp row = warp>>2 (2x32 rows), warp col = warp&3 (4 x TN/4 cols). Kc=64.
// mode 0: +bias -> fp32 C ; 1: swish(+bias) ; 2: swish(+bias + t*w1t) ; 3..6: RK4 stages
template <int TN>
__device__ __noinline__ void gemm_phase(
    const __nv_bfloat16* __restrict__ Ahi, const __nv_bfloat16* __restrict__ Alo,
    const __nv_bfloat16* __restrict__ Whi, const __nv_bfloat16* __restrict__ Wlo,
    const float* __restrict__ bias, float* Cf, __nv_bfloat16* Ohi, __nv_bfloat16* Olo,
    int M, int N, int K, int mode, int tstep, float spc, char* dsm, uint32_t smb) {
    const int tid = threadIdx.x, lane = tid & 31, warp = tid >> 5;
    constexpr int NI = TN / 32;  // n8 tiles per warp (64 -> 2, 32 -> 1)
    const int ncols = N / TN;
    const int ntiles = (M / 64) * ncols;
    const int nk = K / 64;

    const int wm = (warp >> 2) * 32;
    const int wn = (warp & 3) * (TN / 4);

    // ldmatrix per-lane offsets (row stride 144B; 8-lane phases bank-disjoint)
    const uint32_t aoff0 = (uint32_t)(wm + (lane & 15)) * ROWB + (uint32_t)(lane >> 4) * 16;
    const uint32_t aoff1 = aoff0 + 16 * ROWB;
    uint32_t boff;
    if (TN == 64)
        boff = (uint32_t)(wn + (lane & 15)) * ROWB + (uint32_t)(lane >> 4) * 16;
    else
        boff = (uint32_t)(wn + (lane & 7)) * ROWB + (uint32_t)((lane >> 3) & 1) * 16;

    for (int tile = blockIdx.x; tile < ntiles; tile += NCTA) {
        const int rowBase = (tile / ncols) * 64;
        const int colBase = (tile % ncols) * TN;

        float acc[2][NI][4];
#pragma unroll
        for (int mi = 0; mi < 2; mi++)
#pragma unroll
            for (int ni = 0; ni < NI; ni++)
#pragma unroll
                for (int e = 0; e < 4; e++) acc[mi][ni][e] = 0.0f;

        // fill one Kc=64 chunk: 64 rows x 128B per buffer = 512 x 16B; 256 threads x 2
        auto fill = [&](int st, int k0) {
            char* sst = dsm + st * SSZ;
#pragma unroll
            for (int it = 0; it < 2; ++it) {
                const int idx = it * NTHR + tid;
                const int r = idx >> 3, ch = idx & 7;
                const unsigned o = (unsigned)r * ROWB + (unsigned)ch * 16;
                const size_t gA = (size_t)(rowBase + r) * K + k0 + ch * 8;
                cp16cg(sst + o, Ahi + gA);
                cp16cg(sst + BUFSZ + o, Alo + gA);
            }
#pragma unroll
            for (int it = 0; it < (TN == 64 ? 2 : 1); ++it) {
                const int idx = it * NTHR + tid;
                const int r = idx >> 3, ch = idx & 7;
                const unsigned o = (unsigned)r * ROWB + (unsigned)ch * 16;
                const size_t gW = (size_t)(colBase + r) * K + k0 + ch * 8;
                cp16ca(sst + 2 * BUFSZ + o, Whi + gW);
                cp16ca(sst + 3 * BUFSZ + o, Wlo + gW);
            }
            asm volatile("cp.async.commit_group;\n" ::);
        };

        __syncthreads();  // protect stages from previous tile's lagging reads
        fill(0, 0);
        fill(1, 64);

        for (int kt = 0; kt < nk; ++kt) {
            if (kt < nk - 1)
                asm volatile("cp.async.wait_group 1;\n" ::);
            else
                asm volatile("cp.async.wait_group 0;\n" ::);
            __syncthreads();
            if (kt + 2 < nk) fill((kt + 2) % 3, (kt + 2) * 64);
            const uint32_t sb = smb + (uint32_t)(kt % 3) * SSZ;
#pragma unroll
            for (int kk = 0; kk < 4; kk++) {
                const uint32_t cb = sb + kk * 32;
                unsigned a0[4], a1[4], l0[4], l1[4], bh[4], bl[4];
                ldsm4(a0, cb + aoff0);
                ldsm4(a1, cb + aoff1);
                ldsm4(l0, cb + BUFSZ + aoff0);
                ldsm4(l1, cb + BUFSZ + aoff1);
                if (TN == 64) {
                    ldsm4(bh, cb + 2 * BUFSZ + boff);
                    ldsm4(bl, cb + 3 * BUFSZ + boff);
                } else {
                    ldsm2(bh, cb + 2 * BUFSZ + boff);
                    ldsm2(bl, cb + 3 * BUFSZ + boff);
                }
#pragma unroll
                for (int ni = 0; ni < NI; ni++) {
                    const unsigned bh0 = (TN == 64) ? bh[ni] : bh[0];
                    const unsigned bh1 = (TN == 64) ? bh[ni + 2] : bh[1];
                    const unsigned bl0 = (TN == 64) ? bl[ni] : bl[0];
                    const unsigned bl1 = (TN == 64) ? bl[ni + 2] : bl[1];
                    mma16816(acc[0][ni], a0, bh0, bh1);
                    mma16816(acc[0][ni], a0, bl0, bl1);
                    mma16816(acc[0][ni], l0, bh0, bh1);
                    mma16816(acc[1][ni], a1, bh0, bh1);
                    mma16816(acc[1][ni], a1, bl0, bl1);
                    mma16816(acc[1][ni], l1, bh0, bh1);
                }
            }
        }

        // epilogue
#pragma unroll
        for (int mi = 0; mi < 2; mi++) {
#pragma unroll
            for (int half = 0; half < 2; half++) {
                int rr = rowBase + wm + mi * 16 + (lane >> 2) + half * 8;
                float tval = 0.0f, dtv = 0.0f;
                if (mode == 2) tval = g_t0[rr * T_ + tstep] + spc * g_dt[rr * T_ + tstep];
                if (mode >= 3) dtv = g_dt[rr * T_ + tstep];
#pragma unroll
                for (int ni = 0; ni < NI; ni++) {
                    int c = colBase + wn + ni * 8 + (lane & 3) * 2;
                    float v0 = acc[mi][ni][half * 2 + 0] + bias[c];
                    float v1 = acc[mi][ni][half * 2 + 1] + bias[c + 1];
                    if (mode == 0) {
                        float2 o2 = make_float2(v0, v1);
                        *(float2*)&Cf[(size_t)rr * N + c] = o2;
                    } else if (mode <= 2) {
                        if (mode == 2) {
                            v0 += tval * g_w1t[c];
                            v1 += tval * g_w1t[c + 1];
                        }
                        v0 = v0 / (1.0f + __expf(-v0));
                        v1 = v1 / (1.0f + __expf(-v1));
                        split_store2(Ohi, Olo, rr * N + c, v0, v1);
                    } else {
                        int o = rr * H_ + c;
                        float h0 = __ldcg(&g_h[o]), h1 = __ldcg(&g_h[o + 1]);
                        if (mode == 3) {
                            g_kacc[o] = v0;
                            g_kacc[o + 1] = v1;
                            split_store2(g_hin_hi, g_hin_lo, o, h0 + 0.5f * dtv * v0,
                                         h1 + 0.5f * dtv * v1);
                        } else if (mode == 4) {
                            g_kacc[o] = __ldcg(&g_kacc[o]) + 2.0f * v0;
                            g_kacc[o + 1] = __ldcg(&g_kacc[o + 1]) + 2.0f * v1;
                            split_store2(g_hin_hi, g_hin_lo, o, h0 + 0.5f * dtv * v0,
                                         h1 + 0.5f * dtv * v1);
                        } else if (mode == 5) {
                            g_kacc[o] = __ldcg(&g_kacc[o]) + 2.0f * v0;
                            g_kacc[o + 1] = __ldcg(&g_kacc[o + 1]) + 2.0f * v1;
                            split_store2(g_hin_hi, g_hin_lo, o, h0 + dtv * v0, h1 + dtv * v1);
                        } else {
                            float n0 = h0 + (dtv * (1.0f / 6.0f)) * (__ldcg(&g_kacc[o]) + v0);
                            float n1 = h1 + (dtv * (1.0f / 6.0f)) * (__ldcg(&g_kacc[o + 1]) + v1);
                            g_h[o] = n0;
                            g_h[o + 1] = n1;
                            split_store2(g_h_hi, g_h_lo, o, n0, n1);
                        }
                    }
                }
            }
        }
    }
}

__device__ void gate_phase(int t) {
    for (int i = blockIdx.x * NTHR + threadIdx.x; i < B_ * H_; i += NCTA * NTHR) {
        int b = i >> 9, j = i & (H_ - 1);
        const float* gi = g_gi + (size_t)(b * T_ + t) * H3_;
        const float* gh = g_gh + (size_t)b * H3_;
        float ir = __ldcg(&gi[j]), iz = __ldcg(&gi[j + H_]), in = __ldcg(&gi[j + 2 * H_]);
        float hr = __ldcg(&gh[j]), hz = __ldcg(&gh[j + H_]), hn = __ldcg(&gh[j + 2 * H_]);
        float r = 1.0f / (1.0f + expf(-(ir + hr)));
        float z = 1.0f / (1.0f + expf(-(iz + hz)));
        float n = tanhf(in + r * hn);
        float h = (1.0f - z) * n + z * __ldcg(&g_h[i]);
        g_h[i] = h;
        __nv_bfloat16 hh = __float2bfloat16(h);
        g_h_hi[i] = hh;
        g_h_lo[i] = __float2bfloat16(h - __bfloat162float(hh));
    }
}

__global__ void __launch_bounds__(NTHR, 1) k_persist(
    const float* __restrict__ bih, const float* __restrict__ bhh, const float* __restrict__ b1,
    const float* __restrict__ b2, const float* __restrict__ b3, const float* __restrict__ bout,
    float* __restrict__ out) {
    extern __shared__ char dsm[];
    const uint32_t smb = (uint32_t)__cvta_generic_to_shared(dsm);
    unsigned long long bt = 0;

    // gi = x @ Wih^T + bih for all (b,t)
    gemm_phase<64>(g_x_hi, g_x_lo, g_Wihhi, g_Wihlo, bih, g_gi, nullptr, nullptr, B_ * T_, H3_,
                   D_, 0, 0, 0.0f, dsm, smb);
    gbar(bt);

#pragma unroll 1
    for (int t = 0; t < T_; t++) {
#pragma unroll 1
        for (int s = 0; s < 4; s++) {
#pragma unroll 1
            for (int e = 0; e < 4; e++) {
                float spc = (float)s + ((e == 1 || e == 2) ? 0.5f : (e == 3 ? 1.0f : 0.0f));
                const __nv_bfloat16* Ah = e ? g_hin_hi : g_h_hi;
                const __nv_bfloat16* Al = e ? g_hin_lo : g_h_lo;
                gemm_phase<64>(Ah, Al, g_W1hi, g_W1lo, b1, nullptr, g_a1hi, g_a1lo, B_, H2_, H_,
                               2, t, spc, dsm, smb);
                gbar(bt);
                gemm_phase<64>(g_a1hi, g_a1lo, g_W2hi, g_W2lo, b2, nullptr, g_a2hi, g_a2lo, B_,
                               H2_, H2_, 1, t, 0.0f, dsm, smb);
                gbar(bt);
                gemm_phase<32>(g_a2hi, g_a2lo, g_W3hi, g_W3lo, b3, nullptr, nullptr, nullptr,
                               B_, H_, H2_, 3 + e, t, 0.0f, dsm, smb);
                gbar(bt);
            }
        }
        gemm_phase<32>(g_h_hi, g_h_lo, g_Whhhi, g_Whhlo, bhh, g_gh, nullptr, nullptr, B_, H3_,
                       H_, 0, 0, 0.0f, dsm, smb);
        gbar(bt);
        gate_phase(t);
        gbar(bt);
    }

    // out = h @ Wout^T + bout
    gemm_phase<32>(g_h_hi, g_h_lo, g_Wouthi, g_Woutlo, bout, out, nullptr, nullptr, B_,
                   2 * LAT_, H_, 0, 0, 0.0f, dsm, smb);
    // h and c tail regions
    for (int i = blockIdx.x * NTHR + threadIdx.x; i < B_ * H_; i += NCTA * NTHR) {
        out[B_ * 2 * LAT_ + i] = __ldcg(&g_h[i]);
        out[B_ * 2 * LAT_ + B_ * H_ + i] = 0.0f;
    }
}

// ---------------- host ----------------
template <typename Tp>
static Tp* symaddr(const void* sym) {
    void* p = nullptr;
    cudaGetSymbolAddress(&p, sym);
    return (Tp*)p;
}

extern "C" void kernel_launch(void* const* d_in, const int* in_sizes, int n_in,
                              void* d_out, int out_size) {
    const float* x    = (const float*)d_in[0];
    const float* ts   = (const float*)d_in[1];
    const float* Wih  = (const float*)d_in[2];
    const float* Whh  = (const float*)d_in[3];
    const float* bih  = (const float*)d_in[4];
    const float* bhh  = (const float*)d_in[5];
    const float* Wout = (const float*)d_in[6];
    const float* bout = (const float*)d_in[7];
    const float* W1   = (const float*)d_in[8];
    const float* b1   = (const float*)d_in[9];
    const float* W2   = (const float*)d_in[10];
    const float* b2   = (const float*)d_in[11];
    const float* W3   = (const float*)d_in[12];
    const float* b3   = (const float*)d_in[13];
    float* out = (float*)d_out;

    cudaFuncSetAttribute(k_persist, cudaFuncAttributeMaxDynamicSharedMemorySize, SMEM_TOTAL);

    const int TPB = 256;
    k_split<<<(H3_ * D_ + TPB - 1) / TPB, TPB>>>(Wih, symaddr<__nv_bfloat16>(g_Wihhi),
                                                 symaddr<__nv_bfloat16>(g_Wihlo), H3_ * D_);
    k_split<<<(H3_ * H_ + TPB - 1) / TPB, TPB>>>(Whh, symaddr<__nv_bfloat16>(g_Whhhi),
                                                 symaddr<__nv_bfloat16>(g_Whhlo), H3_ * H_);
    k_split<<<(H2_ * H2_ + TPB - 1) / TPB, TPB>>>(W2, symaddr<__nv_bfloat16>(g_W2hi),
                                                  symaddr<__nv_bfloat16>(g_W2lo), H2_ * H2_);
    k_split<<<(H_ * H2_ + TPB - 1) / TPB, TPB>>>(W3, symaddr<__nv_bfloat16>(g_W3hi),
                                                 symaddr<__nv_bfloat16>(g_W3lo), H_ * H2_);
    k_split<<<(2 * LAT_ * H_ + TPB - 1) / TPB, TPB>>>(Wout, symaddr<__nv_bfloat16>(g_Wouthi),
                                                      symaddr<__nv_bfloat16>(g_Woutlo),
                                                      2 * LAT_ * H_);
    k_split<<<(B_ * T_ * D_ + TPB - 1) / TPB, TPB>>>(x, symaddr<__nv_bfloat16>(g_x_hi),
                                                     symaddr<__nv_bfloat16>(g_x_lo),
                                                     B_ * T_ * D_);
    k_split_w1<<<(H2_ * H_ + TPB - 1) / TPB, TPB>>>(W1);
    k_tprep<<<(B_ * T_ + TPB - 1) / TPB, TPB>>>(ts);
    k_reset<<<(B_ * H_ + TPB - 1) / TPB, TPB>>>();

    k_persist<<<NCTA, NTHR, SMEM_TOTAL>>>(bih, bhh, b1, b2, b3, bout, out);
}